// round 3
// baseline (speedup 1.0000x reference)
#include <cuda_runtime.h>
#include <math.h>

#define NCLUST 196
#define DIM 256
#define NROWS 262144
#define WINDOW 2048            // rows per segsum block (2 MB)
#define TEMP_INV 2.0f          // 1/TEMPERATURE
#define EPSV 1e-12f

// -------- scratch (device globals; no allocation allowed) --------
__device__ float g_sums[2][NCLUST * DIM];     // [q,k] segment sums
__device__ float g_centers[2][NCLUST * DIM];  // normalized centers
__device__ int   g_counts[NCLUST];
__device__ float g_loss[NCLUST];

// -------- 1. zero scratch --------
__global__ void k_zero() {
    int i = blockIdx.x * blockDim.x + threadIdx.x;
    int stride = gridDim.x * blockDim.x;
    float* s = &g_sums[0][0];
    for (int k = i; k < 2 * NCLUST * DIM; k += stride) s[k] = 0.0f;
    for (int k = i; k < NCLUST; k += stride) g_counts[k] = 0;
}

// -------- 2. histogram of labels (int4-vectorized) --------
__global__ void k_hist(const int* __restrict__ labels) {
    __shared__ int s_cnt[NCLUST];
    for (int i = threadIdx.x; i < NCLUST; i += blockDim.x) s_cnt[i] = 0;
    __syncthreads();
    const int4* l4 = (const int4*)labels;
    for (int r = blockIdx.x * blockDim.x + threadIdx.x; r < NROWS / 4;
         r += gridDim.x * blockDim.x) {
        int4 v = l4[r];
        atomicAdd(&s_cnt[v.x], 1);
        atomicAdd(&s_cnt[v.y], 1);
        atomicAdd(&s_cnt[v.z], 1);
        atomicAdd(&s_cnt[v.w], 1);
    }
    __syncthreads();
    for (int i = threadIdx.x; i < NCLUST; i += blockDim.x)
        if (s_cnt[i]) atomicAdd(&g_counts[i], s_cnt[i]);
}

// -------- 3. fused local-sort segment sum (hot kernel) --------
// grid (NROWS/WINDOW, 2). Block counting-sorts its 2048-row window by label
// in SMEM, then gathers rows within its private 2 MB window in sorted order.
// Thread t: dim-quad 4*(t&63), row subgroup t>>6 (stride 4 over sorted seq).
// Register float4 run accumulator; warp-uniform red.v4 flush on label change.
__global__ void __launch_bounds__(256) k_segsum(const float* __restrict__ xq,
                                                const float* __restrict__ xk,
                                                const int* __restrict__ labels) {
    __shared__ int s_hist[NCLUST];
    __shared__ int s_off[NCLUST];
    __shared__ unsigned int s_pack[WINDOW];   // (label<<16) | local_row_idx

    const int t = threadIdx.x;
    const int r0 = blockIdx.x * WINDOW;
    const float* __restrict__ x = blockIdx.y ? xk : xq;
    float* sums = &g_sums[blockIdx.y][0];

    // --- Phase A: local counting sort of labels[r0 .. r0+2048) ---
    for (int i = t; i < NCLUST; i += 256) s_hist[i] = 0;
    __syncthreads();
    int labs[8];
#pragma unroll
    for (int u = 0; u < 8; u++) labs[u] = labels[r0 + u * 256 + t];
#pragma unroll
    for (int u = 0; u < 8; u++) atomicAdd(&s_hist[labs[u]], 1);
    __syncthreads();
    if (t == 0) {
        int acc = 0;
        for (int c = 0; c < NCLUST; c++) { s_off[c] = acc; acc += s_hist[c]; }
    }
    __syncthreads();
#pragma unroll
    for (int u = 0; u < 8; u++) {
        int c = labs[u];
        int p = atomicAdd(&s_off[c], 1);
        s_pack[p] = ((unsigned)c << 16) | (unsigned)(u * 256 + t);
    }
    __syncthreads();

    // --- Phase B: gather within the 2 MB window, run-accumulate, flush ---
    const int dq = (t & 63) * 4;      // dim-quad base
    const int sub = t >> 6;           // 0..3 (uniform within a warp)
    const float* __restrict__ xw = x + (size_t)r0 * DIM;

    unsigned first = s_pack[sub];
    int cur = (int)(first >> 16);
    float4 acc = make_float4(0.f, 0.f, 0.f, 0.f);

    for (int base = 0; base < WINDOW; base += 32) {
        unsigned pk[8];
        float4 v[8];
#pragma unroll
        for (int u = 0; u < 8; u++) pk[u] = s_pack[base + u * 4 + sub];
#pragma unroll
        for (int u = 0; u < 8; u++)
            v[u] = *(const float4*)&xw[(size_t)(pk[u] & 0xFFFFu) * DIM + dq];
#pragma unroll
        for (int u = 0; u < 8; u++) {
            int lb = (int)(pk[u] >> 16);
            if (lb != cur) {              // warp-uniform branch
                float* dst = &sums[cur * DIM + dq];
                asm volatile("red.global.add.v4.f32 [%0], {%1,%2,%3,%4};"
                             :: "l"(dst), "f"(acc.x), "f"(acc.y),
                                "f"(acc.z), "f"(acc.w) : "memory");
                acc = make_float4(0.f, 0.f, 0.f, 0.f);
                cur = lb;
            }
            acc.x += v[u].x;
            acc.y += v[u].y;
            acc.z += v[u].z;
            acc.w += v[u].w;
        }
    }
    {
        float* dst = &sums[cur * DIM + dq];
        asm volatile("red.global.add.v4.f32 [%0], {%1,%2,%3,%4};"
                     :: "l"(dst), "f"(acc.x), "f"(acc.y),
                        "f"(acc.z), "f"(acc.w) : "memory");
    }
}

// -------- 4. centers: mean + L2 normalize. grid (196, 2) x 256 thr --------
__global__ void k_centers() {
    int c = blockIdx.x;
    int m = blockIdx.y;
    int tid = threadIdx.x;
    int lane = tid & 31, w = tid >> 5;
    float cnt = (float)g_counts[c];
    float v = g_sums[m][c * DIM + tid] / fmaxf(cnt, EPSV);
    float t = v * v;
#pragma unroll
    for (int off = 16; off > 0; off >>= 1)
        t += __shfl_xor_sync(0xFFFFFFFFu, t, off);
    __shared__ float sr[8];
    __shared__ float s_norm;
    if (lane == 0) sr[w] = t;
    __syncthreads();
    if (tid == 0) {
        float tot = 0.0f;
        for (int i = 0; i < 8; i++) tot += sr[i];
        s_norm = sqrtf(tot);
    }
    __syncthreads();
    g_centers[m][c * DIM + tid] = v / fmaxf(s_norm, EPSV);
}

// -------- 5. per-row contrastive loss. grid 196 x 256 thr --------
__global__ void k_loss() {
    const int i = blockIdx.x;
    const int tid = threadIdx.x;
    const int lane = tid & 31, w = tid >> 5;
    __shared__ float s_qi[DIM];
    __shared__ float s_row[NCLUST + 1];   // [0..195] row, [196] = pos (d_k)
    __shared__ float s_red[8];
    __shared__ float s_mx, s_sum;

    s_qi[tid] = g_centers[0][i * DIM + tid];
    __syncthreads();

    for (int jj = w; jj <= NCLUST; jj += 8) {
        const float* vec = (jj == NCLUST) ? &g_centers[1][i * DIM]
                                          : &g_centers[0][jj * DIM];
        float p = 0.0f;
#pragma unroll
        for (int m = 0; m < 8; m++)
            p += s_qi[m * 32 + lane] * vec[m * 32 + lane];
#pragma unroll
        for (int off = 16; off > 0; off >>= 1)
            p += __shfl_xor_sync(0xFFFFFFFFu, p, off);
        if (lane == 0) s_row[jj] = p * TEMP_INV;
    }
    __syncthreads();

    if (tid < NCLUST) {
        float r = (tid == i) ? s_row[NCLUST] : s_row[tid];
        if (g_counts[tid] == 0) r = -10.0f;
        s_row[tid] = r;
    }
    __syncthreads();

    float v = (tid < NCLUST) ? s_row[tid] : -1e30f;
#pragma unroll
    for (int off = 16; off > 0; off >>= 1)
        v = fmaxf(v, __shfl_xor_sync(0xFFFFFFFFu, v, off));
    if (lane == 0) s_red[w] = v;
    __syncthreads();
    if (tid == 0) {
        float mx = s_red[0];
        for (int k = 1; k < 8; k++) mx = fmaxf(mx, s_red[k]);
        s_mx = mx;
    }
    __syncthreads();
    float mx = s_mx;

    float e = (tid < NCLUST) ? __expf(s_row[tid] - mx) : 0.0f;
#pragma unroll
    for (int off = 16; off > 0; off >>= 1)
        e += __shfl_xor_sync(0xFFFFFFFFu, e, off);
    if (lane == 0) s_red[w] = e;
    __syncthreads();
    if (tid == 0) {
        float tot = 0.0f;
        for (int k = 0; k < 8; k++) tot += s_red[k];
        s_sum = tot;
    }
    __syncthreads();

    if (tid == 0) {
        if (g_counts[i] == 0)
            g_loss[i] = 0.0f;
        else
            g_loss[i] = -s_row[i] + mx + logf(s_sum);
    }
}

// -------- 6. final reduce: mean over non-empty clusters --------
__global__ void k_final(float* out) {
    const int tid = threadIdx.x;
    const int lane = tid & 31, w = tid >> 5;
    float v = (tid < NCLUST) ? g_loss[tid] : 0.0f;
    float z = (tid < NCLUST && g_counts[tid] == 0) ? 1.0f : 0.0f;
#pragma unroll
    for (int off = 16; off > 0; off >>= 1) {
        v += __shfl_xor_sync(0xFFFFFFFFu, v, off);
        z += __shfl_xor_sync(0xFFFFFFFFu, z, off);
    }
    __shared__ float sv[8], sz[8];
    if (lane == 0) { sv[w] = v; sz[w] = z; }
    __syncthreads();
    if (tid == 0) {
        float tv = 0.0f, tz = 0.0f;
        for (int k = 0; k < 8; k++) { tv += sv[k]; tz += sz[k]; }
        out[0] = tv / ((float)NCLUST - tz);
    }
}

extern "C" void kernel_launch(void* const* d_in, const int* in_sizes, int n_in,
                              void* d_out, int out_size) {
    const float* im_q = (const float*)d_in[0];
    const float* im_k = (const float*)d_in[1];
    const int* labels = (const int*)d_in[2];
    float* out = (float*)d_out;

    k_zero<<<64, 256>>>();
    k_hist<<<256, 256>>>(labels);
    dim3 gs(NROWS / WINDOW, 2);
    k_segsum<<<gs, 256>>>(im_q, im_k, labels);
    dim3 gc(NCLUST, 2);
    k_centers<<<gc, 256>>>();
    k_loss<<<NCLUST, 256>>>();
    k_final<<<1, 256>>>(out);
}

// round 4
// speedup vs baseline: 1.1967x; 1.1967x over previous
#include <cuda_runtime.h>
#include <math.h>

#define NCLUST 196
#define DIM 256
#define NROWS 262144
#define TEMP_INV 2.0f        // 1/TEMPERATURE
#define EPSV 1e-12f

// -------- scratch (device globals; no allocation allowed) --------
__device__ float g_sums[2][NCLUST * DIM];       // [q,k] raw segment sums
__device__ int   g_counts[NCLUST];
__device__ int   g_cursor[NCLUST];
__device__ unsigned g_pack[NROWS];              // (label<<18) | row
__device__ float g_loss[NCLUST];

// -------- 1. histogram of labels (int4-vectorized) --------
__global__ void k_hist(const int* __restrict__ labels) {
    __shared__ int s_cnt[NCLUST];
    for (int i = threadIdx.x; i < NCLUST; i += blockDim.x) s_cnt[i] = 0;
    __syncthreads();
    const int4* l4 = (const int4*)labels;
    for (int r = blockIdx.x * blockDim.x + threadIdx.x; r < NROWS / 4;
         r += gridDim.x * blockDim.x) {
        int4 v = l4[r];
        atomicAdd(&s_cnt[v.x], 1);
        atomicAdd(&s_cnt[v.y], 1);
        atomicAdd(&s_cnt[v.z], 1);
        atomicAdd(&s_cnt[v.w], 1);
    }
    __syncthreads();
    for (int i = threadIdx.x; i < NCLUST; i += blockDim.x)
        if (s_cnt[i]) atomicAdd(&g_counts[i], s_cnt[i]);
}

// -------- 2. exclusive scan -> cursor (1 block, parallel) --------
__global__ void k_scan() {
    __shared__ int s[256];
    int t = threadIdx.x;
    int v = (t < NCLUST) ? g_counts[t] : 0;
    s[t] = v;
    __syncthreads();
#pragma unroll
    for (int off = 1; off < 256; off <<= 1) {
        int add = (t >= off) ? s[t - off] : 0;
        __syncthreads();
        s[t] += add;
        __syncthreads();
    }
    if (t < NCLUST) g_cursor[t] = s[t] - v;   // exclusive
}

// -------- 3. scatter: rank from phase-1 atomic return --------
// grid 256 x 256 thr, each block owns 1024 contiguous rows.
__global__ void k_scatter(const int* __restrict__ labels) {
    __shared__ int s_hist[NCLUST];
    __shared__ int s_base[NCLUST];
    int t = threadIdx.x;
    for (int i = t; i < NCLUST; i += 256) s_hist[i] = 0;
    __syncthreads();
    int r0 = blockIdx.x * 1024;
    int labs[4], rk[4];
#pragma unroll
    for (int u = 0; u < 4; u++) labs[u] = labels[r0 + u * 256 + t];
#pragma unroll
    for (int u = 0; u < 4; u++) rk[u] = atomicAdd(&s_hist[labs[u]], 1);
    __syncthreads();
    for (int i = t; i < NCLUST; i += 256) {
        int h = s_hist[i];
        if (h) s_base[i] = atomicAdd(&g_cursor[i], h);
    }
    __syncthreads();
#pragma unroll
    for (int u = 0; u < 4; u++) {
        int c = labs[u];
        int p = s_base[c] + rk[u];
        g_pack[p] = ((unsigned)c << 18) | (unsigned)(r0 + u * 256 + t);
    }
}

// -------- 4. segment sums over label-sorted rows (hot kernel) --------
// grid (1024, 2): x = 256-entry chunk of sorted order, y = matrix (q/k).
// Thread t: dim-quad 4*(t&63), sorted sub-stream t>>6 (stride 4).
// float4 register accumulator; atomic flush only at cluster boundaries.
__global__ void __launch_bounds__(256) k_segsum(const float* __restrict__ xq,
                                                const float* __restrict__ xk) {
    const float* __restrict__ x = blockIdx.y ? xk : xq;
    float* sums = &g_sums[blockIdx.y][0];
    const int t = threadIdx.x;
    const int dq = (t & 63) * 4;      // dim-quad base
    const int sub = t >> 6;           // 0..3
    const int start = blockIdx.x * 256;

    int cur = (int)(g_pack[start + sub] >> 18);
    float4 acc = make_float4(0.f, 0.f, 0.f, 0.f);

    for (int it = 0; it < 64; it += 8) {
        unsigned pk[8];
        float4 v[8];
#pragma unroll
        for (int u = 0; u < 8; u++)
            pk[u] = g_pack[start + sub + (it + u) * 4];
#pragma unroll
        for (int u = 0; u < 8; u++)
            v[u] = *(const float4*)&x[(size_t)(pk[u] & 0x3FFFFu) * DIM + dq];
#pragma unroll
        for (int u = 0; u < 8; u++) {
            int lb = (int)(pk[u] >> 18);
            if (lb != cur) {
                float* dst = &sums[cur * DIM + dq];
                atomicAdd(dst + 0, acc.x);
                atomicAdd(dst + 1, acc.y);
                atomicAdd(dst + 2, acc.z);
                atomicAdd(dst + 3, acc.w);
                acc = make_float4(0.f, 0.f, 0.f, 0.f);
                cur = lb;
            }
            acc.x += v[u].x;
            acc.y += v[u].y;
            acc.z += v[u].z;
            acc.w += v[u].w;
        }
    }
    float* dst = &sums[cur * DIM + dq];
    atomicAdd(dst + 0, acc.x);
    atomicAdd(dst + 1, acc.y);
    atomicAdd(dst + 2, acc.z);
    atomicAdd(dst + 3, acc.w);
}

// -------- 5. fused centers+loss. grid 196 x 256 thr --------
// center_j = s_j / max(||s_j||, eps)  (count divide cancels in normalize)
__global__ void k_loss() {
    const int i = blockIdx.x;
    const int tid = threadIdx.x;
    const int lane = tid & 31, w = tid >> 5;
    __shared__ float s_qi[DIM];
    __shared__ float s_row[NCLUST];
    __shared__ float s_red[8];
    __shared__ float s_nqi, s_dk, s_mx, s_sum;

    const float* sq = &g_sums[0][0];
    const float* sk = &g_sums[1][0];

    // load raw q-sum row i; reduce its normsq and dot/normsq with k-sum row i
    float qv = sq[i * DIM + tid];
    float kv = sk[i * DIM + tid];
    s_qi[tid] = qv;
    float a = qv * qv;       // normsq_q partial
    float b = qv * kv;       // dot(q,k) partial
    float c = kv * kv;       // normsq_k partial
#pragma unroll
    for (int off = 16; off > 0; off >>= 1) {
        a += __shfl_xor_sync(0xFFFFFFFFu, a, off);
        b += __shfl_xor_sync(0xFFFFFFFFu, b, off);
        c += __shfl_xor_sync(0xFFFFFFFFu, c, off);
    }
    __shared__ float ra[8], rb[8], rc[8];
    if (lane == 0) { ra[w] = a; rb[w] = b; rc[w] = c; }
    __syncthreads();
    if (tid == 0) {
        float ta = 0, tb = 0, tc = 0;
        for (int k = 0; k < 8; k++) { ta += ra[k]; tb += rb[k]; tc += rc[k]; }
        float nq = fmaxf(sqrtf(ta), EPSV);
        float nk = fmaxf(sqrtf(tc), EPSV);
        s_nqi = nq;
        s_dk = tb / (nq * nk) * TEMP_INV;
    }
    __syncthreads();
    const float nqi = s_nqi;

    // each warp: rows jj = w, w+8, ... compute dot(s_qi, s_qj) and ||s_qj||
    for (int jj = w; jj < NCLUST; jj += 8) {
        const float* vec = &sq[jj * DIM];
        float p = 0.0f, n = 0.0f;
#pragma unroll
        for (int m = 0; m < 8; m++) {
            float vj = vec[m * 32 + lane];
            p += s_qi[m * 32 + lane] * vj;
            n += vj * vj;
        }
#pragma unroll
        for (int off = 16; off > 0; off >>= 1) {
            p += __shfl_xor_sync(0xFFFFFFFFu, p, off);
            n += __shfl_xor_sync(0xFFFFFFFFu, n, off);
        }
        if (lane == 0) {
            float nj = fmaxf(sqrtf(n), EPSV);
            s_row[jj] = p / (nqi * nj) * TEMP_INV;
        }
    }
    __syncthreads();

    // mask: diag <- d_k; empty columns <- -10
    if (tid < NCLUST) {
        float r = (tid == i) ? s_dk : s_row[tid];
        if (g_counts[tid] == 0) r = -10.0f;
        s_row[tid] = r;
    }
    __syncthreads();

    // block max
    float v = (tid < NCLUST) ? s_row[tid] : -1e30f;
#pragma unroll
    for (int off = 16; off > 0; off >>= 1)
        v = fmaxf(v, __shfl_xor_sync(0xFFFFFFFFu, v, off));
    if (lane == 0) s_red[w] = v;
    __syncthreads();
    if (tid == 0) {
        float mx = s_red[0];
        for (int k = 1; k < 8; k++) mx = fmaxf(mx, s_red[k]);
        s_mx = mx;
    }
    __syncthreads();
    float mx = s_mx;

    float e = (tid < NCLUST) ? __expf(s_row[tid] - mx) : 0.0f;
#pragma unroll
    for (int off = 16; off > 0; off >>= 1)
        e += __shfl_xor_sync(0xFFFFFFFFu, e, off);
    if (lane == 0) s_red[w] = e;
    __syncthreads();
    if (tid == 0) {
        float tot = 0.0f;
        for (int k = 0; k < 8; k++) tot += s_red[k];
        s_sum = tot;
    }
    __syncthreads();

    if (tid == 0) {
        if (g_counts[i] == 0)
            g_loss[i] = 0.0f;
        else
            g_loss[i] = -s_row[i] + mx + logf(s_sum);
    }
}

// -------- 6. final reduce: mean over non-empty clusters --------
__global__ void k_final(float* out) {
    const int tid = threadIdx.x;
    const int lane = tid & 31, w = tid >> 5;
    float v = (tid < NCLUST) ? g_loss[tid] : 0.0f;
    float z = (tid < NCLUST && g_counts[tid] == 0) ? 1.0f : 0.0f;
#pragma unroll
    for (int off = 16; off > 0; off >>= 1) {
        v += __shfl_xor_sync(0xFFFFFFFFu, v, off);
        z += __shfl_xor_sync(0xFFFFFFFFu, z, off);
    }
    __shared__ float sv[8], sz[8];
    if (lane == 0) { sv[w] = v; sz[w] = z; }
    __syncthreads();
    if (tid == 0) {
        float tv = 0.0f, tz = 0.0f;
        for (int k = 0; k < 8; k++) { tv += sv[k]; tz += sz[k]; }
        out[0] = tv / ((float)NCLUST - tz);
    }
}

extern "C" void kernel_launch(void* const* d_in, const int* in_sizes, int n_in,
                              void* d_out, int out_size) {
    const float* im_q = (const float*)d_in[0];
    const float* im_k = (const float*)d_in[1];
    const int* labels = (const int*)d_in[2];
    float* out = (float*)d_out;

    void *p_sums = 0, *p_counts = 0;
    cudaGetSymbolAddress(&p_sums, g_sums);
    cudaGetSymbolAddress(&p_counts, g_counts);
    cudaMemsetAsync(p_sums, 0, sizeof(float) * 2 * NCLUST * DIM);
    cudaMemsetAsync(p_counts, 0, sizeof(int) * NCLUST);

    k_hist<<<256, 256>>>(labels);
    k_scan<<<1, 256>>>();
    k_scatter<<<256, 256>>>(labels);
    dim3 gs(NROWS / 256, 2);
    k_segsum<<<gs, 256>>>(im_q, im_k);
    k_loss<<<NCLUST, 256>>>();
    k_final<<<1, 256>>>(out);
}

// round 5
// speedup vs baseline: 1.1990x; 1.0019x over previous
#include <cuda_runtime.h>
#include <math.h>

#define NCLUST 196
#define DIM 256
#define NROWS 262144
#define TEMP_INV 2.0f        // 1/TEMPERATURE
#define EPSV 1e-12f

// -------- scratch (device globals; no allocation allowed) --------
__device__ float g_sums[2][NCLUST * DIM];       // [q,k] raw segment sums
struct Meta {
    int counts[NCLUST];
    int cursor[NCLUST];
    int done;
    float loss_sum;
};
__device__ Meta g_m;                            // zeroed by one memset
__device__ unsigned g_pack[NROWS];              // (label<<18) | row

// -------- 1. histogram of labels (int4-vectorized) --------
__global__ void k_hist(const int* __restrict__ labels) {
    __shared__ int s_cnt[NCLUST];
    for (int i = threadIdx.x; i < NCLUST; i += blockDim.x) s_cnt[i] = 0;
    __syncthreads();
    const int4* l4 = (const int4*)labels;
    for (int r = blockIdx.x * blockDim.x + threadIdx.x; r < NROWS / 4;
         r += gridDim.x * blockDim.x) {
        int4 v = l4[r];
        atomicAdd(&s_cnt[v.x], 1);
        atomicAdd(&s_cnt[v.y], 1);
        atomicAdd(&s_cnt[v.z], 1);
        atomicAdd(&s_cnt[v.w], 1);
    }
    __syncthreads();
    for (int i = threadIdx.x; i < NCLUST; i += blockDim.x)
        if (s_cnt[i]) atomicAdd(&g_m.counts[i], s_cnt[i]);
}

// -------- 2. scatter (scan fused in). grid 512 x 256, 512 rows/block ----
__global__ void k_scatter(const int* __restrict__ labels) {
    __shared__ int s_hist[NCLUST];
    __shared__ int s_base[NCLUST];
    __shared__ int s_scan[256];
    int t = threadIdx.x;

    // per-block exclusive prefix of global counts (cheap, redundant per block)
    int cv = (t < NCLUST) ? g_m.counts[t] : 0;
    s_scan[t] = cv;
    for (int i = t; i < NCLUST; i += 256) s_hist[i] = 0;
    __syncthreads();
#pragma unroll
    for (int off = 1; off < 256; off <<= 1) {
        int add = (t >= off) ? s_scan[t - off] : 0;
        __syncthreads();
        s_scan[t] += add;
        __syncthreads();
    }
    // s_scan[t] now inclusive; exclusive = s_scan[t] - cv

    int r0 = blockIdx.x * 512;
    int labs[2], rk[2];
#pragma unroll
    for (int u = 0; u < 2; u++) labs[u] = labels[r0 + u * 256 + t];
#pragma unroll
    for (int u = 0; u < 2; u++) rk[u] = atomicAdd(&s_hist[labs[u]], 1);
    __syncthreads();
    if (t < NCLUST) {
        int h = s_hist[t];
        if (h) s_base[t] = (s_scan[t] - cv) + atomicAdd(&g_m.cursor[t], h);
    }
    __syncthreads();
#pragma unroll
    for (int u = 0; u < 2; u++) {
        int c = labs[u];
        int p = s_base[c] + rk[u];
        g_pack[p] = ((unsigned)c << 18) | (unsigned)(r0 + u * 256 + t);
    }
}

// -------- 3. segment sums over label-sorted rows (hot kernel) --------
// grid (1024, 2): x = 256-entry chunk of sorted order, y = matrix (q/k).
// Thread t: dim-quad 4*(t&63), sorted sub-stream t>>6 (stride 4).
// Streaming (evict-first) float4 gathers; atomic flush at run boundaries.
__global__ void __launch_bounds__(256, 5) k_segsum(const float* __restrict__ xq,
                                                   const float* __restrict__ xk) {
    const float* __restrict__ x = blockIdx.y ? xk : xq;
    float* sums = &g_sums[blockIdx.y][0];
    const int t = threadIdx.x;
    const int dq = (t & 63) * 4;      // dim-quad base
    const int sub = t >> 6;           // 0..3
    const int start = blockIdx.x * 256;

    int cur = (int)(g_pack[start + sub] >> 18);
    float4 acc = make_float4(0.f, 0.f, 0.f, 0.f);

    for (int it = 0; it < 64; it += 8) {
        unsigned pk[8];
        float4 v[8];
#pragma unroll
        for (int u = 0; u < 8; u++)
            pk[u] = g_pack[start + sub + (it + u) * 4];
#pragma unroll
        for (int u = 0; u < 8; u++)
            v[u] = __ldcs((const float4*)&x[(size_t)(pk[u] & 0x3FFFFu) * DIM + dq]);
#pragma unroll
        for (int u = 0; u < 8; u++) {
            int lb = (int)(pk[u] >> 18);
            if (lb != cur) {
                float* dst = &sums[cur * DIM + dq];
                atomicAdd(dst + 0, acc.x);
                atomicAdd(dst + 1, acc.y);
                atomicAdd(dst + 2, acc.z);
                atomicAdd(dst + 3, acc.w);
                acc = make_float4(0.f, 0.f, 0.f, 0.f);
                cur = lb;
            }
            acc.x += v[u].x;
            acc.y += v[u].y;
            acc.z += v[u].z;
            acc.w += v[u].w;
        }
    }
    float* dst = &sums[cur * DIM + dq];
    atomicAdd(dst + 0, acc.x);
    atomicAdd(dst + 1, acc.y);
    atomicAdd(dst + 2, acc.z);
    atomicAdd(dst + 3, acc.w);
}

// -------- 4. fused centers+loss+final. grid 196 x 256 thr --------
// center_j = s_j / max(||s_j||, eps)  (count divide cancels in normalize)
// Last block (ticket) produces the final mean.
__global__ void k_loss(float* out) {
    const int i = blockIdx.x;
    const int tid = threadIdx.x;
    const int lane = tid & 31, w = tid >> 5;
    __shared__ float s_qi[DIM];
    __shared__ float s_row[NCLUST];
    __shared__ float s_red[8];
    __shared__ float s_nqi, s_dk, s_mx, s_sum;

    const float* sq = &g_sums[0][0];
    const float* sk = &g_sums[1][0];

    float qv = sq[i * DIM + tid];
    float kv = sk[i * DIM + tid];
    s_qi[tid] = qv;
    float a = qv * qv;       // normsq_q partial
    float b = qv * kv;       // dot(q,k) partial
    float c = kv * kv;       // normsq_k partial
#pragma unroll
    for (int off = 16; off > 0; off >>= 1) {
        a += __shfl_xor_sync(0xFFFFFFFFu, a, off);
        b += __shfl_xor_sync(0xFFFFFFFFu, b, off);
        c += __shfl_xor_sync(0xFFFFFFFFu, c, off);
    }
    __shared__ float ra[8], rb[8], rc[8];
    if (lane == 0) { ra[w] = a; rb[w] = b; rc[w] = c; }
    __syncthreads();
    if (tid == 0) {
        float ta = 0, tb = 0, tc = 0;
        for (int k = 0; k < 8; k++) { ta += ra[k]; tb += rb[k]; tc += rc[k]; }
        float nq = fmaxf(sqrtf(ta), EPSV);
        float nk = fmaxf(sqrtf(tc), EPSV);
        s_nqi = nq;
        s_dk = tb / (nq * nk) * TEMP_INV;
    }
    __syncthreads();
    const float nqi = s_nqi;

    for (int jj = w; jj < NCLUST; jj += 8) {
        const float* vec = &sq[jj * DIM];
        float p = 0.0f, n = 0.0f;
#pragma unroll
        for (int m = 0; m < 8; m++) {
            float vj = vec[m * 32 + lane];
            p += s_qi[m * 32 + lane] * vj;
            n += vj * vj;
        }
#pragma unroll
        for (int off = 16; off > 0; off >>= 1) {
            p += __shfl_xor_sync(0xFFFFFFFFu, p, off);
            n += __shfl_xor_sync(0xFFFFFFFFu, n, off);
        }
        if (lane == 0) {
            float nj = fmaxf(sqrtf(n), EPSV);
            s_row[jj] = p / (nqi * nj) * TEMP_INV;
        }
    }
    __syncthreads();

    if (tid < NCLUST) {
        float r = (tid == i) ? s_dk : s_row[tid];
        if (g_m.counts[tid] == 0) r = -10.0f;
        s_row[tid] = r;
    }
    __syncthreads();

    float v = (tid < NCLUST) ? s_row[tid] : -1e30f;
#pragma unroll
    for (int off = 16; off > 0; off >>= 1)
        v = fmaxf(v, __shfl_xor_sync(0xFFFFFFFFu, v, off));
    if (lane == 0) s_red[w] = v;
    __syncthreads();
    if (tid == 0) {
        float mx = s_red[0];
        for (int k = 1; k < 8; k++) mx = fmaxf(mx, s_red[k]);
        s_mx = mx;
    }
    __syncthreads();
    float mx = s_mx;

    float e = (tid < NCLUST) ? __expf(s_row[tid] - mx) : 0.0f;
#pragma unroll
    for (int off = 16; off > 0; off >>= 1)
        e += __shfl_xor_sync(0xFFFFFFFFu, e, off);
    if (lane == 0) s_red[w] = e;
    __syncthreads();
    if (tid == 0) {
        float tot = 0.0f;
        for (int k = 0; k < 8; k++) tot += s_red[k];
        s_sum = tot;
    }
    __syncthreads();

    if (tid == 0) {
        float loss = 0.0f;
        if (g_m.counts[i] != 0)
            loss = -s_row[i] + mx + logf(s_sum);
        if (loss != 0.0f) atomicAdd(&g_m.loss_sum, loss);
        __threadfence();
        int ticket = atomicAdd(&g_m.done, 1);
        if (ticket == NCLUST - 1) {
            // all prior blocks' atomics are visible
            float tot = atomicAdd(&g_m.loss_sum, 0.0f);
            int nz = 0;
            for (int k = 0; k < NCLUST; k++)
                if (g_m.counts[k] == 0) nz++;
            out[0] = tot / ((float)NCLUST - (float)nz);
        }
    }
}

extern "C" void kernel_launch(void* const* d_in, const int* in_sizes, int n_in,
                              void* d_out, int out_size) {
    const float* im_q = (const float*)d_in[0];
    const float* im_k = (const float*)d_in[1];
    const int* labels = (const int*)d_in[2];
    float* out = (float*)d_out;

    void *p_sums = 0, *p_meta = 0;
    cudaGetSymbolAddress(&p_sums, g_sums);
    cudaGetSymbolAddress(&p_meta, g_m);
    cudaMemsetAsync(p_sums, 0, sizeof(float) * 2 * NCLUST * DIM);
    cudaMemsetAsync(p_meta, 0, sizeof(Meta));

    k_hist<<<256, 256>>>(labels);
    k_scatter<<<512, 256>>>(labels);
    dim3 gs(NROWS / 256, 2);
    k_segsum<<<gs, 256>>>(im_q, im_k);
    k_loss<<<NCLUST, 256>>>(out);
}

// round 6
// speedup vs baseline: 1.2066x; 1.0064x over previous
#include <cuda_runtime.h>
#include <math.h>

#define NCLUST 196
#define DIM 256
#define NROWS 262144
#define TEMP_INV 2.0f        // 1/TEMPERATURE
#define EPSV 1e-12f

// -------- scratch (device globals; no allocation allowed) --------
__device__ float g_sums[2][NCLUST * DIM];       // [q,k] raw segment sums
__device__ float g_cent[2][NCLUST * DIM];       // normalized centers
struct Meta {
    int counts[NCLUST];
    int cursor[NCLUST];
    int done;
    float loss_sum;
};
__device__ Meta g_m;                            // zeroed by one memset
__device__ unsigned g_pack[NROWS];              // (label<<18) | row

// -------- 1. histogram of labels (int4-vectorized) --------
__global__ void k_hist(const int* __restrict__ labels) {
    __shared__ int s_cnt[NCLUST];
    for (int i = threadIdx.x; i < NCLUST; i += blockDim.x) s_cnt[i] = 0;
    __syncthreads();
    const int4* l4 = (const int4*)labels;
    for (int r = blockIdx.x * blockDim.x + threadIdx.x; r < NROWS / 4;
         r += gridDim.x * blockDim.x) {
        int4 v = l4[r];
        atomicAdd(&s_cnt[v.x], 1);
        atomicAdd(&s_cnt[v.y], 1);
        atomicAdd(&s_cnt[v.z], 1);
        atomicAdd(&s_cnt[v.w], 1);
    }
    __syncthreads();
    for (int i = threadIdx.x; i < NCLUST; i += blockDim.x)
        if (s_cnt[i]) atomicAdd(&g_m.counts[i], s_cnt[i]);
}

// -------- 2. scatter (scan fused in). grid 512 x 256, 512 rows/block ----
__global__ void k_scatter(const int* __restrict__ labels) {
    __shared__ int s_hist[NCLUST];
    __shared__ int s_base[NCLUST];
    __shared__ int s_scan[256];
    int t = threadIdx.x;

    int cv = (t < NCLUST) ? g_m.counts[t] : 0;
    s_scan[t] = cv;
    for (int i = t; i < NCLUST; i += 256) s_hist[i] = 0;
    __syncthreads();
#pragma unroll
    for (int off = 1; off < 256; off <<= 1) {
        int add = (t >= off) ? s_scan[t - off] : 0;
        __syncthreads();
        s_scan[t] += add;
        __syncthreads();
    }

    int r0 = blockIdx.x * 512;
    int labs[2], rk[2];
#pragma unroll
    for (int u = 0; u < 2; u++) labs[u] = labels[r0 + u * 256 + t];
#pragma unroll
    for (int u = 0; u < 2; u++) rk[u] = atomicAdd(&s_hist[labs[u]], 1);
    __syncthreads();
    if (t < NCLUST) {
        int h = s_hist[t];
        if (h) s_base[t] = (s_scan[t] - cv) + atomicAdd(&g_m.cursor[t], h);
    }
    __syncthreads();
#pragma unroll
    for (int u = 0; u < 2; u++) {
        int c = labs[u];
        int p = s_base[c] + rk[u];
        g_pack[p] = ((unsigned)c << 18) | (unsigned)(r0 + u * 256 + t);
    }
}

// -------- 3. segment sums over label-sorted rows (hot kernel) --------
__global__ void __launch_bounds__(256, 5) k_segsum(const float* __restrict__ xq,
                                                   const float* __restrict__ xk) {
    const float* __restrict__ x = blockIdx.y ? xk : xq;
    float* sums = &g_sums[blockIdx.y][0];
    const int t = threadIdx.x;
    const int dq = (t & 63) * 4;      // dim-quad base
    const int sub = t >> 6;           // 0..3
    const int start = blockIdx.x * 256;

    int cur = (int)(g_pack[start + sub] >> 18);
    float4 acc = make_float4(0.f, 0.f, 0.f, 0.f);

    for (int it = 0; it < 64; it += 8) {
        unsigned pk[8];
        float4 v[8];
#pragma unroll
        for (int u = 0; u < 8; u++)
            pk[u] = g_pack[start + sub + (it + u) * 4];
#pragma unroll
        for (int u = 0; u < 8; u++)
            v[u] = __ldcs((const float4*)&x[(size_t)(pk[u] & 0x3FFFFu) * DIM + dq]);
#pragma unroll
        for (int u = 0; u < 8; u++) {
            int lb = (int)(pk[u] >> 18);
            if (lb != cur) {
                float* dst = &sums[cur * DIM + dq];
                atomicAdd(dst + 0, acc.x);
                atomicAdd(dst + 1, acc.y);
                atomicAdd(dst + 2, acc.z);
                atomicAdd(dst + 3, acc.w);
                acc = make_float4(0.f, 0.f, 0.f, 0.f);
                cur = lb;
            }
            acc.x += v[u].x;
            acc.y += v[u].y;
            acc.z += v[u].z;
            acc.w += v[u].w;
        }
    }
    float* dst = &sums[cur * DIM + dq];
    atomicAdd(dst + 0, acc.x);
    atomicAdd(dst + 1, acc.y);
    atomicAdd(dst + 2, acc.z);
    atomicAdd(dst + 3, acc.w);
}

// -------- 4. normalize: one warp per (matrix,cluster) row. grid 98x128 ----
// center = s / max(||s||, eps)   (count divide cancels)
__global__ void k_centers() {
    int gw = blockIdx.x * 4 + (threadIdx.x >> 5);   // 0..391
    int lane = threadIdx.x & 31;
    int m = gw >= NCLUST;
    int c = m ? gw - NCLUST : gw;
    const float4* src = (const float4*)&g_sums[m][c * DIM];
    float4* dst = (float4*)&g_cent[m][c * DIM];
    float4 a = src[lane];
    float4 b = src[32 + lane];
    float n = a.x * a.x + a.y * a.y + a.z * a.z + a.w * a.w
            + b.x * b.x + b.y * b.y + b.z * b.z + b.w * b.w;
#pragma unroll
    for (int off = 16; off > 0; off >>= 1)
        n += __shfl_xor_sync(0xFFFFFFFFu, n, off);
    float inv = 1.0f / fmaxf(sqrtf(n), EPSV);
    a.x *= inv; a.y *= inv; a.z *= inv; a.w *= inv;
    b.x *= inv; b.y *= inv; b.z *= inv; b.w *= inv;
    dst[lane] = a;
    dst[32 + lane] = b;
}

// -------- 5. loss: 2 rows per block. grid 98 x 256 thr, ticket final ----
__global__ void k_loss(float* out) {
    const int i0 = blockIdx.x * 2;
    const int i1 = i0 + 1;
    const int tid = threadIdx.x;
    const int lane = tid & 31, w = tid >> 5;
    __shared__ float s_q0[DIM], s_q1[DIM];
    __shared__ float s_row0[NCLUST], s_row1[NCLUST];
    __shared__ float s_dk[2];
    __shared__ float s_r0[8], s_r1[8];
    __shared__ float s_mx0, s_mx1, s_sum0, s_sum1;

    const float* qc = &g_cent[0][0];
    const float* kc = &g_cent[1][0];

    s_q0[tid] = qc[i0 * DIM + tid];
    s_q1[tid] = qc[i1 * DIM + tid];
    __syncthreads();

    const float4* q0v = (const float4*)s_q0;
    const float4* q1v = (const float4*)s_q1;
    float4 a0 = q0v[lane], b0 = q0v[32 + lane];
    float4 a1 = q1v[lane], b1 = q1v[32 + lane];

    // warps cover j = w, w+8, ...; each j reused for both i0 and i1
    for (int j = w; j < NCLUST; j += 8) {
        const float4* vj = (const float4*)&qc[j * DIM];
        float4 va = vj[lane], vb = vj[32 + lane];
        float p0 = va.x * a0.x + va.y * a0.y + va.z * a0.z + va.w * a0.w
                 + vb.x * b0.x + vb.y * b0.y + vb.z * b0.z + vb.w * b0.w;
        float p1 = va.x * a1.x + va.y * a1.y + va.z * a1.z + va.w * a1.w
                 + vb.x * b1.x + vb.y * b1.y + vb.z * b1.z + vb.w * b1.w;
#pragma unroll
        for (int off = 16; off > 0; off >>= 1) {
            p0 += __shfl_xor_sync(0xFFFFFFFFu, p0, off);
            p1 += __shfl_xor_sync(0xFFFFFFFFu, p1, off);
        }
        if (lane == 0) {
            s_row0[j] = p0 * TEMP_INV;
            s_row1[j] = p1 * TEMP_INV;
        }
    }
    // d_k diagonals: warp 0 -> i0, warp 1 -> i1
    if (w < 2) {
        const float4* vj = (const float4*)&kc[(w ? i1 : i0) * DIM];
        float4 va = vj[lane], vb = vj[32 + lane];
        float4 ca = w ? a1 : a0, cb = w ? b1 : b0;
        float p = va.x * ca.x + va.y * ca.y + va.z * ca.z + va.w * ca.w
                + vb.x * cb.x + vb.y * cb.y + vb.z * cb.z + vb.w * cb.w;
#pragma unroll
        for (int off = 16; off > 0; off >>= 1)
            p += __shfl_xor_sync(0xFFFFFFFFu, p, off);
        if (lane == 0) s_dk[w] = p * TEMP_INV;
    }
    __syncthreads();

    // mask: diag <- d_k; empty columns <- -10
    if (tid < NCLUST) {
        int zero = (g_m.counts[tid] == 0);
        float r0 = (tid == i0) ? s_dk[0] : s_row0[tid];
        float r1 = (tid == i1) ? s_dk[1] : s_row1[tid];
        if (zero) { r0 = -10.0f; r1 = -10.0f; }
        s_row0[tid] = r0;
        s_row1[tid] = r1;
    }
    __syncthreads();

    // joint max reduce
    float v0 = (tid < NCLUST) ? s_row0[tid] : -1e30f;
    float v1 = (tid < NCLUST) ? s_row1[tid] : -1e30f;
#pragma unroll
    for (int off = 16; off > 0; off >>= 1) {
        v0 = fmaxf(v0, __shfl_xor_sync(0xFFFFFFFFu, v0, off));
        v1 = fmaxf(v1, __shfl_xor_sync(0xFFFFFFFFu, v1, off));
    }
    if (lane == 0) { s_r0[w] = v0; s_r1[w] = v1; }
    __syncthreads();
    if (tid == 0) {
        float m0 = s_r0[0], m1 = s_r1[0];
        for (int k = 1; k < 8; k++) {
            m0 = fmaxf(m0, s_r0[k]);
            m1 = fmaxf(m1, s_r1[k]);
        }
        s_mx0 = m0; s_mx1 = m1;
    }
    __syncthreads();
    float mx0 = s_mx0, mx1 = s_mx1;

    float e0 = (tid < NCLUST) ? __expf(s_row0[tid] - mx0) : 0.0f;
    float e1 = (tid < NCLUST) ? __expf(s_row1[tid] - mx1) : 0.0f;
#pragma unroll
    for (int off = 16; off > 0; off >>= 1) {
        e0 += __shfl_xor_sync(0xFFFFFFFFu, e0, off);
        e1 += __shfl_xor_sync(0xFFFFFFFFu, e1, off);
    }
    if (lane == 0) { s_r0[w] = e0; s_r1[w] = e1; }
    __syncthreads();
    if (tid == 0) {
        float t0 = 0.f, t1 = 0.f;
        for (int k = 0; k < 8; k++) { t0 += s_r0[k]; t1 += s_r1[k]; }
        s_sum0 = t0; s_sum1 = t1;
    }
    __syncthreads();

    if (tid == 0) {
        float loss = 0.0f;
        if (g_m.counts[i0] != 0) loss += -s_row0[i0] + mx0 + logf(s_sum0);
        if (g_m.counts[i1] != 0) loss += -s_row1[i1] + mx1 + logf(s_sum1);
        if (loss != 0.0f) atomicAdd(&g_m.loss_sum, loss);
        __threadfence();
        int ticket = atomicAdd(&g_m.done, 1);
        if (ticket == NCLUST / 2 - 1) {
            float tot = atomicAdd(&g_m.loss_sum, 0.0f);
            int nz = 0;
            for (int k = 0; k < NCLUST; k++)
                if (g_m.counts[k] == 0) nz++;
            out[0] = tot / ((float)NCLUST - (float)nz);
        }
    }
}

extern "C" void kernel_launch(void* const* d_in, const int* in_sizes, int n_in,
                              void* d_out, int out_size) {
    const float* im_q = (const float*)d_in[0];
    const float* im_k = (const float*)d_in[1];
    const int* labels = (const int*)d_in[2];
    float* out = (float*)d_out;

    void *p_sums = 0, *p_meta = 0;
    cudaGetSymbolAddress(&p_sums, g_sums);
    cudaGetSymbolAddress(&p_meta, g_m);
    cudaMemsetAsync(p_sums, 0, sizeof(float) * 2 * NCLUST * DIM);
    cudaMemsetAsync(p_meta, 0, sizeof(Meta));

    k_hist<<<256, 256>>>(labels);
    k_scatter<<<512, 256>>>(labels);
    dim3 gs(NROWS / 256, 2);
    k_segsum<<<gs, 256>>>(im_q, im_k);
    k_centers<<<98, 128>>>();
    k_loss<<<NCLUST / 2, 256>>>(out);
}